// round 2
// baseline (speedup 1.0000x reference)
#include <cuda_runtime.h>
#include <cuda_bf16.h>
#include <cstdint>
#include <cstddef>

#define NQ  4096
#define EMB 768
#define HID 1024
#define MEM 65536

// ---------------- static device scratch (no allocations allowed) ----------------
__device__ __nv_bfloat16 g_qh[NQ*EMB],        g_ql[NQ*EMB];
__device__ __nv_bfloat16 g_Winh[EMB*HID],     g_Winl[EMB*HID];
__device__ __nv_bfloat16 g_We1h[HID*2*HID],   g_We1l[HID*2*HID];
__device__ __nv_bfloat16 g_We2h[2*HID*HID],   g_We2l[2*HID*HID];
__device__ __nv_bfloat16 g_Wkh[HID*HID],      g_Wkl[HID*HID];
__device__ __nv_bfloat16 g_Wr1h[2*HID*2*HID], g_Wr1l[2*HID*2*HID];
__device__ __nv_bfloat16 g_Wr2h[2*HID*EMB],   g_Wr2l[2*HID*EMB];
__device__ __nv_bfloat16 g_MKT[(size_t)HID*MEM];   // mem_keys^T  [HID][MEM] bf16
__device__ __nv_bfloat16 g_MV [(size_t)MEM*HID];   // mem_values  [MEM][HID] bf16
__device__ __nv_bfloat16 g_xh[NQ*HID],   g_xl[NQ*HID];
__device__ __nv_bfloat16 g_hh[NQ*2*HID], g_hl[NQ*2*HID];
__device__ __nv_bfloat16 g_ch[NQ*2*HID], g_cl[NQ*2*HID];   // combined = [encoded | retrieved]
__device__ __nv_bfloat16 g_key[NQ*HID];
__device__ __nv_bfloat16 g_P[(size_t)NQ*MEM];              // exp(logits) bf16, 512MB
__device__ __nv_bfloat16 g_rh[NQ*2*HID], g_rl[NQ*2*HID];
__device__ float         g_rowsum[NQ];

// ---------------- small helpers ----------------
__device__ __forceinline__ void cpasync16(uint32_t saddr, const void* g) {
    asm volatile("cp.async.cg.shared.global [%0], [%1], 16;\n" :: "r"(saddr), "l"(g));
}
__device__ __forceinline__ void ldsm4(uint32_t r[4], uint32_t addr) {
    asm volatile("ldmatrix.sync.aligned.m8n8.x4.shared.b16 {%0,%1,%2,%3}, [%4];\n"
        : "=r"(r[0]), "=r"(r[1]), "=r"(r[2]), "=r"(r[3]) : "r"(addr));
}
__device__ __forceinline__ void ldsm4t(uint32_t r[4], uint32_t addr) {
    asm volatile("ldmatrix.sync.aligned.m8n8.x4.trans.shared.b16 {%0,%1,%2,%3}, [%4];\n"
        : "=r"(r[0]), "=r"(r[1]), "=r"(r[2]), "=r"(r[3]) : "r"(addr));
}
__device__ __forceinline__ void mma_bf16(float c[4], const uint32_t a[4], uint32_t b0, uint32_t b1) {
    asm volatile(
        "mma.sync.aligned.m16n8k16.row.col.f32.bf16.bf16.f32 "
        "{%0,%1,%2,%3}, {%4,%5,%6,%7}, {%8,%9}, {%0,%1,%2,%3};\n"
        : "+f"(c[0]), "+f"(c[1]), "+f"(c[2]), "+f"(c[3])
        : "r"(a[0]), "r"(a[1]), "r"(a[2]), "r"(a[3]), "r"(b0), "r"(b1));
}
__device__ __forceinline__ float gelu_erf(float x) {
    return 0.5f * x * (1.0f + erff(x * 0.70710678118654752f));
}

// ---------------- generic bf16 tensor-core GEMM ----------------
// C[M,N] = A[M,K] @ B[K,N], A row-major, B row-major(K,N). fp32 accumulate.
// SPLIT: use (Ah+Al)(Bh+Bl) ~ AhBh + AhBl + AlBh (3 mma) for near-fp32 accuracy.
// EPI: 0 bias->f32 out | 1 bias->hi/lo bf16 | 2 bias+gelu->hi/lo | 3 bias->bf16
//      4 exp(acc*scale)->bf16 | 5 acc*(1/rowsum[row])->hi/lo
template<bool SPLIT, int EPI>
__global__ void __launch_bounds__(256, 1) gemm_bf16(
    const __nv_bfloat16* __restrict__ Ah, const __nv_bfloat16* __restrict__ Al,
    const __nv_bfloat16* __restrict__ Bh, const __nv_bfloat16* __restrict__ Bl,
    const float* __restrict__ bias,
    float* __restrict__ outF, __nv_bfloat16* __restrict__ outHi, __nv_bfloat16* __restrict__ outLo,
    const float* __restrict__ rowsum, float scale,
    int M, int N, int K, int lda, int ldb, int ldc)
{
    constexpr int STAGE = SPLIT ? 32768 : 16384;   // [Ah 8K][Bh 8K]([Al 8K][Bl 8K])
    extern __shared__ char smem[];
    const uint32_t sb = (uint32_t)__cvta_generic_to_shared(smem);
    const int tid  = threadIdx.x;
    const int lane = tid & 31, wid = tid >> 5;
    const int wm = wid & 3, wn = wid >> 2;          // 4x2 warp grid, warp tile 32x64
    const int m0 = blockIdx.y << 7, n0 = blockIdx.x << 7;

    float acc[2][8][4];
    #pragma unroll
    for (int i = 0; i < 2; i++)
        #pragma unroll
        for (int j = 0; j < 8; j++)
            #pragma unroll
            for (int q = 0; q < 4; q++) acc[i][j][q] = 0.f;

    const int nkb = K >> 5;

    // per-thread gmem->smem chunk mapping (16B chunks)
    const int a_r0 = tid >> 2, a_kc = tid & 3;   // A: 128 rows x 4 chunks; 2 chunks/thread
    const int b_r0 = tid >> 4, b_nc = tid & 15;  // B:  32 rows x 16 chunks; 2 chunks/thread
    uint32_t a_off[2], b_off[2];
    #pragma unroll
    for (int i = 0; i < 2; i++) {
        int ar = a_r0 + i * 64;
        // A packed: 64 phys rows x 128B, rows 2r/2r+1 interleaved, XOR swizzle -> conflict-free LDSM
        a_off[i] = (uint32_t)(((ar >> 1) * 128) + ((((a_kc + ((ar & 1) << 2)) ^ ((ar >> 1) & 7))) << 4));
        int br = b_r0 + i * 16;
        b_off[i] = (uint32_t)(8192 + br * 256 + (((b_nc ^ (br & 7))) << 4));
    }

    auto LOAD = [&](int s, int kb) {
        const int k0 = kb << 5;
        const uint32_t base = sb + s * STAGE;
        #pragma unroll
        for (int i = 0; i < 2; i++) {
            int ar = a_r0 + i * 64;
            const __nv_bfloat16* gp = Ah + (size_t)(m0 + ar) * lda + (k0 + a_kc * 8);
            cpasync16(base + a_off[i], gp);
            if (SPLIT) cpasync16(base + 16384 + a_off[i],
                                 Al + (size_t)(m0 + ar) * lda + (k0 + a_kc * 8));
        }
        #pragma unroll
        for (int i = 0; i < 2; i++) {
            int br = b_r0 + i * 16;
            const __nv_bfloat16* gp = Bh + (size_t)(k0 + br) * ldb + (n0 + b_nc * 8);
            cpasync16(base + b_off[i], gp);
            if (SPLIT) cpasync16(base + 16384 + b_off[i],
                                 Bl + (size_t)(k0 + br) * ldb + (n0 + b_nc * 8));
        }
    };

    LOAD(0, 0);
    asm volatile("cp.async.commit_group;\n" ::);

    for (int kb = 0; kb < nkb; kb++) {
        if (kb + 1 < nkb) LOAD((kb + 1) & 1, kb + 1);
        asm volatile("cp.async.commit_group;\n" ::);
        asm volatile("cp.async.wait_group 1;\n" ::: "memory");
        __syncthreads();

        const uint32_t base = sb + (kb & 1) * STAGE;
        #pragma unroll
        for (int ks = 0; ks < 2; ks++) {
            uint32_t a[2][4], al[2][4], b[4][4], bl[4][4];
            #pragma unroll
            for (int mt = 0; mt < 2; mt++) {
                int row = wm * 32 + mt * 16 + (lane & 15);
                int kch = ks * 2 + ((lane >> 4) & 1);
                uint32_t off = (uint32_t)(((row >> 1) * 128) +
                               ((((kch + ((row & 1) << 2)) ^ ((row >> 1) & 7))) << 4));
                ldsm4(a[mt], base + off);
                if (SPLIT) ldsm4(al[mt], base + 16384 + off);
            }
            {
                int grp = lane >> 3;
                int krow = ks * 16 + (lane & 7) + ((grp & 1) << 3);
                int ncb  = wn * 64 + ((grp & 2) << 2);
                #pragma unroll
                for (int u = 0; u < 4; u++) {
                    int ncol = ncb + u * 16;
                    uint32_t off = (uint32_t)(8192 + krow * 256 +
                                   ((((ncol >> 3) ^ (krow & 7))) << 4));
                    ldsm4t(b[u], base + off);
                    if (SPLIT) ldsm4t(bl[u], base + 16384 + off);
                }
            }
            #pragma unroll
            for (int mt = 0; mt < 2; mt++) {
                #pragma unroll
                for (int u = 0; u < 4; u++) {
                    mma_bf16(acc[mt][2*u],   a[mt], b[u][0], b[u][1]);
                    mma_bf16(acc[mt][2*u+1], a[mt], b[u][2], b[u][3]);
                    if (SPLIT) {
                        mma_bf16(acc[mt][2*u],   al[mt], b[u][0], b[u][1]);
                        mma_bf16(acc[mt][2*u+1], al[mt], b[u][2], b[u][3]);
                        mma_bf16(acc[mt][2*u],   a[mt], bl[u][0], bl[u][1]);
                        mma_bf16(acc[mt][2*u+1], a[mt], bl[u][2], bl[u][3]);
                    }
                }
            }
        }
        __syncthreads();
    }

    // -------- epilogue --------
    const int g = lane >> 2, t = lane & 3;
    #pragma unroll
    for (int mt = 0; mt < 2; mt++) {
        #pragma unroll
        for (int h2 = 0; h2 < 2; h2++) {
            const int row = m0 + wm * 32 + mt * 16 + g + h2 * 8;
            float inv = 1.f;
            if (EPI == 5) inv = 1.0f / rowsum[row];
            #pragma unroll
            for (int j = 0; j < 8; j++) {
                const int col = n0 + wn * 64 + j * 8 + t * 2;
                float v0 = acc[mt][j][h2 * 2 + 0];
                float v1 = acc[mt][j][h2 * 2 + 1];
                if (EPI <= 3) { v0 += bias[col]; v1 += bias[col + 1]; }
                if (EPI == 2) { v0 = gelu_erf(v0); v1 = gelu_erf(v1); }
                if (EPI == 4) { v0 = __expf(v0 * scale); v1 = __expf(v1 * scale); }
                if (EPI == 5) { v0 *= inv; v1 *= inv; }
                const size_t idx = (size_t)row * ldc + col;
                if (EPI == 0) {
                    float2 f; f.x = v0; f.y = v1;
                    *reinterpret_cast<float2*>(outF + idx) = f;
                } else if (EPI == 3 || EPI == 4) {
                    __nv_bfloat162 hv; hv.x = __float2bfloat16(v0); hv.y = __float2bfloat16(v1);
                    *reinterpret_cast<__nv_bfloat162*>(outHi + idx) = hv;
                } else {
                    __nv_bfloat162 hv; hv.x = __float2bfloat16(v0); hv.y = __float2bfloat16(v1);
                    *reinterpret_cast<__nv_bfloat162*>(outHi + idx) = hv;
                    __nv_bfloat162 lv;
                    lv.x = __float2bfloat16(v0 - __bfloat162float(hv.x));
                    lv.y = __float2bfloat16(v1 - __bfloat162float(hv.y));
                    *reinterpret_cast<__nv_bfloat162*>(outLo + idx) = lv;
                }
            }
        }
    }
}

// ---------------- conversion kernels ----------------
__global__ void k_split(const float* __restrict__ s, __nv_bfloat16* __restrict__ hi,
                        __nv_bfloat16* __restrict__ lo, int n)
{
    for (int i = blockIdx.x * blockDim.x + threadIdx.x; i < n; i += gridDim.x * blockDim.x) {
        float v = s[i];
        __nv_bfloat16 h = __float2bfloat16(v);
        hi[i] = h;
        lo[i] = __float2bfloat16(v - __bfloat162float(h));
    }
}
__global__ void k_tobf16(const float* __restrict__ s, __nv_bfloat16* __restrict__ d, size_t n)
{
    for (size_t i = blockIdx.x * (size_t)blockDim.x + threadIdx.x; i < n;
         i += (size_t)gridDim.x * blockDim.x)
        d[i] = __float2bfloat16(s[i]);
}
// mem_keys [MEM][HID] f32 -> g_MKT [HID][MEM] bf16
__global__ void k_transpose_bf16(const float* __restrict__ src, __nv_bfloat16* __restrict__ dst)
{
    __shared__ __nv_bfloat16 tile[32][33];
    const int r0 = blockIdx.y << 5;   // MEM base
    const int c0 = blockIdx.x << 5;   // HID base
    #pragma unroll
    for (int i = 0; i < 4; i++) {
        int r = threadIdx.y + i * 8;
        tile[r][threadIdx.x] = __float2bfloat16(src[(size_t)(r0 + r) * HID + c0 + threadIdx.x]);
    }
    __syncthreads();
    #pragma unroll
    for (int i = 0; i < 4; i++) {
        int c = threadIdx.y + i * 8;
        dst[(size_t)(c0 + c) * MEM + r0 + threadIdx.x] = tile[threadIdx.x][c];
    }
}
// deterministic per-row sum of bf16 P (one CTA per row)
__global__ void k_rowsum(const __nv_bfloat16* __restrict__ P, float* __restrict__ rs)
{
    __shared__ float red[8];
    const int row = blockIdx.x;
    const uint4* p4 = reinterpret_cast<const uint4*>(P + (size_t)row * MEM);
    float s = 0.f;
    for (int i = threadIdx.x; i < MEM / 8; i += blockDim.x) {
        uint4 v = p4[i];
        uint32_t w[4] = {v.x, v.y, v.z, v.w};
        #pragma unroll
        for (int q = 0; q < 4; q++) {
            __nv_bfloat162 b = *reinterpret_cast<const __nv_bfloat162*>(&w[q]);
            float2 f = __bfloat1622float2(b);
            s += f.x + f.y;
        }
    }
    #pragma unroll
    for (int o = 16; o > 0; o >>= 1) s += __shfl_xor_sync(0xffffffffu, s, o);
    if ((threadIdx.x & 31) == 0) red[threadIdx.x >> 5] = s;
    __syncthreads();
    if (threadIdx.x == 0) {
        float t = 0.f;
        #pragma unroll
        for (int q = 0; q < 8; q++) t += red[q];
        rs[row] = t;
    }
}

// ---------------- launch ----------------
#define DEVPTR(name, sym, type) \
    type* name; { void* p_ = nullptr; cudaGetSymbolAddress(&p_, sym); name = (type*)p_; }

extern "C" void kernel_launch(void* const* d_in, const int* in_sizes, int n_in,
                              void* d_out, int out_size)
{
    (void)in_sizes; (void)n_in; (void)out_size;
    const float* query = (const float*)d_in[0];
    const float* W_in  = (const float*)d_in[1];
    const float* b_in  = (const float*)d_in[2];
    const float* W_e1  = (const float*)d_in[3];
    const float* b_e1  = (const float*)d_in[4];
    const float* W_e2  = (const float*)d_in[5];
    const float* b_e2  = (const float*)d_in[6];
    const float* W_k   = (const float*)d_in[7];
    const float* b_k   = (const float*)d_in[8];
    const float* mem_keys   = (const float*)d_in[9];
    const float* mem_values = (const float*)d_in[10];
    const float* W_r1  = (const float*)d_in[11];
    const float* b_r1  = (const float*)d_in[12];
    const float* W_r2  = (const float*)d_in[13];
    const float* b_r2  = (const float*)d_in[14];
    float* out = (float*)d_out;

    DEVPTR(qh, g_qh, __nv_bfloat16)   DEVPTR(ql, g_ql, __nv_bfloat16)
    DEVPTR(Winh, g_Winh, __nv_bfloat16) DEVPTR(Winl, g_Winl, __nv_bfloat16)
    DEVPTR(We1h, g_We1h, __nv_bfloat16) DEVPTR(We1l, g_We1l, __nv_bfloat16)
    DEVPTR(We2h, g_We2h, __nv_bfloat16) DEVPTR(We2l, g_We2l, __nv_bfloat16)
    DEVPTR(Wkh, g_Wkh, __nv_bfloat16)   DEVPTR(Wkl, g_Wkl, __nv_bfloat16)
    DEVPTR(Wr1h, g_Wr1h, __nv_bfloat16) DEVPTR(Wr1l, g_Wr1l, __nv_bfloat16)
    DEVPTR(Wr2h, g_Wr2h, __nv_bfloat16) DEVPTR(Wr2l, g_Wr2l, __nv_bfloat16)
    DEVPTR(MKT, g_MKT, __nv_bfloat16)   DEVPTR(MV, g_MV, __nv_bfloat16)
    DEVPTR(xh, g_xh, __nv_bfloat16)     DEVPTR(xl, g_xl, __nv_bfloat16)
    DEVPTR(hh, g_hh, __nv_bfloat16)     DEVPTR(hl, g_hl, __nv_bfloat16)
    DEVPTR(ch, g_ch, __nv_bfloat16)     DEVPTR(cl, g_cl, __nv_bfloat16)
    DEVPTR(key, g_key, __nv_bfloat16)
    DEVPTR(P, g_P, __nv_bfloat16)
    DEVPTR(rh, g_rh, __nv_bfloat16)     DEVPTR(rl, g_rl, __nv_bfloat16)
    DEVPTR(rowsum, g_rowsum, float)

    cudaFuncSetAttribute(gemm_bf16<true,0>, cudaFuncAttributeMaxDynamicSharedMemorySize, 65536);
    cudaFuncSetAttribute(gemm_bf16<true,1>, cudaFuncAttributeMaxDynamicSharedMemorySize, 65536);
    cudaFuncSetAttribute(gemm_bf16<true,2>, cudaFuncAttributeMaxDynamicSharedMemorySize, 65536);
    cudaFuncSetAttribute(gemm_bf16<true,3>, cudaFuncAttributeMaxDynamicSharedMemorySize, 65536);

    // ---- conversions ----
    k_split<<<(NQ*EMB + 255) / 256, 256>>>(query, qh, ql, NQ*EMB);
    k_split<<<(EMB*HID + 255) / 256, 256>>>(W_in, Winh, Winl, EMB*HID);
    k_split<<<(HID*2*HID + 255) / 256, 256>>>(W_e1, We1h, We1l, HID*2*HID);
    k_split<<<(2*HID*HID + 255) / 256, 256>>>(W_e2, We2h, We2l, 2*HID*HID);
    k_split<<<(HID*HID + 255) / 256, 256>>>(W_k, Wkh, Wkl, HID*HID);
    k_split<<<(2*HID*2*HID + 255) / 256, 256>>>(W_r1, Wr1h, Wr1l, 2*HID*2*HID);
    k_split<<<(2*HID*EMB + 255) / 256, 256>>>(W_r2, Wr2h, Wr2l, 2*HID*EMB);
    k_tobf16<<<8192, 256>>>(mem_values, MV, (size_t)MEM * HID);
    k_transpose_bf16<<<dim3(HID/32, MEM/32), dim3(32, 8)>>>(mem_keys, MKT);

    // ---- GEMM chain ----
    // x = query @ W_in + b_in
    gemm_bf16<true,1><<<dim3(HID/128, NQ/128), 256, 65536>>>(
        qh, ql, Winh, Winl, b_in, nullptr, xh, xl, nullptr, 0.f,
        NQ, HID, EMB, EMB, HID, HID);
    // h = gelu(x @ W_e1 + b_e1)
    gemm_bf16<true,2><<<dim3(2*HID/128, NQ/128), 256, 65536>>>(
        xh, xl, We1h, We1l, b_e1, nullptr, hh, hl, nullptr, 0.f,
        NQ, 2*HID, HID, HID, 2*HID, 2*HID);
    // encoded = h @ W_e2 + b_e2  -> combined[:, 0:HID]  (ldc = 2*HID)
    gemm_bf16<true,1><<<dim3(HID/128, NQ/128), 256, 65536>>>(
        hh, hl, We2h, We2l, b_e2, nullptr, ch, cl, nullptr, 0.f,
        NQ, HID, 2*HID, 2*HID, HID, 2*HID);
    // key = encoded @ W_k + b_k  (A = combined left half, lda = 2*HID) -> bf16
    gemm_bf16<true,3><<<dim3(HID/128, NQ/128), 256, 65536>>>(
        ch, cl, Wkh, Wkl, b_k, nullptr, key, nullptr, nullptr, 0.f,
        NQ, HID, HID, 2*HID, HID, HID);
    // P = exp((key @ mem_keys^T) / 32)   [NQ, MEM] bf16
    gemm_bf16<false,4><<<dim3(MEM/128, NQ/128), 256, 32768>>>(
        key, nullptr, MKT, nullptr, nullptr, nullptr, P, nullptr, nullptr, 0.03125f,
        NQ, MEM, HID, HID, MEM, MEM);
    // rowsum[r] = sum_c P[r,c]   (deterministic)
    k_rowsum<<<NQ, 256>>>(P, rowsum);
    // retrieved = (P @ mem_values) / rowsum -> combined[:, HID:2*HID]
    gemm_bf16<false,5><<<dim3(HID/128, NQ/128), 256, 32768>>>(
        P, nullptr, MV, nullptr, nullptr, nullptr, ch + HID, cl + HID, rowsum, 0.f,
        NQ, HID, MEM, MEM, HID, 2*HID);
    // r = gelu(combined @ W_r1 + b_r1)
    gemm_bf16<true,2><<<dim3(2*HID/128, NQ/128), 256, 65536>>>(
        ch, cl, Wr1h, Wr1l, b_r1, nullptr, rh, rl, nullptr, 0.f,
        NQ, 2*HID, 2*HID, 2*HID, 2*HID, 2*HID);
    // result = r @ W_r2 + b_r2  -> fp32 out
    gemm_bf16<true,0><<<dim3(EMB/128, NQ/128), 256, 65536>>>(
        rh, rl, Wr2h, Wr2l, b_r2, out, nullptr, nullptr, nullptr, 0.f,
        NQ, EMB, 2*HID, 2*HID, EMB, EMB);
}

// round 4
// speedup vs baseline: 1.4356x; 1.4356x over previous
#include <cuda_runtime.h>
#include <cuda_bf16.h>
#include <cstdint>
#include <cstddef>

#define NQ  4096
#define EMB 768
#define HID 1024
#define MEM 65536
#define KSPLIT 4
#define BM 128
#define BN 256
#define BK 64
#define NT_LOGITS (MEM / BN)   // 256 n-tiles in logits GEMM

// ---------------- static device scratch ----------------
__device__ __nv_bfloat16 g_qh[NQ*EMB],        g_ql[NQ*EMB];
__device__ __nv_bfloat16 g_Winh[HID*EMB],     g_Winl[HID*EMB];      // weights transposed: [N][K]
__device__ __nv_bfloat16 g_We1h[2*HID*HID],   g_We1l[2*HID*HID];
__device__ __nv_bfloat16 g_We2h[HID*2*HID],   g_We2l[HID*2*HID];
__device__ __nv_bfloat16 g_Wkh[HID*HID],      g_Wkl[HID*HID];
__device__ __nv_bfloat16 g_Wr1h[2*HID*2*HID], g_Wr1l[2*HID*2*HID];
__device__ __nv_bfloat16 g_Wr2h[EMB*2*HID],   g_Wr2l[EMB*2*HID];
__device__ __nv_bfloat16 g_MK [(size_t)MEM*HID];    // mem_keys bf16 [MEM][HID]  (= [N][K])
__device__ __nv_bfloat16 g_MVT[(size_t)HID*MEM];    // mem_values^T [HID][MEM]   (= [N][K])
__device__ __nv_bfloat16 g_xh[NQ*HID],   g_xl[NQ*HID];
__device__ __nv_bfloat16 g_hh[NQ*2*HID], g_hl[NQ*2*HID];
__device__ __nv_bfloat16 g_ch[NQ*2*HID], g_cl[NQ*2*HID];   // combined = [encoded | retrieved]
__device__ __nv_bfloat16 g_key[NQ*HID];
__device__ __nv_bfloat16 g_P[(size_t)NQ*MEM];              // exp(logits/32) bf16
__device__ __nv_bfloat16 g_rh[NQ*2*HID], g_rl[NQ*2*HID];
__device__ float         g_part[(size_t)KSPLIT*NQ*HID];    // split-K partials
__device__ float         g_prs[(size_t)NQ*NT_LOGITS];      // per-tile rowsum partials
__device__ float         g_rowsum[NQ];

// ---------------- helpers ----------------
__device__ __forceinline__ void cpasync16(uint32_t saddr, const void* g) {
    asm volatile("cp.async.cg.shared.global [%0], [%1], 16;\n" :: "r"(saddr), "l"(g));
}
__device__ __forceinline__ void ldsm4(uint32_t* r, uint32_t addr) {
    asm volatile("ldmatrix.sync.aligned.m8n8.x4.shared.b16 {%0,%1,%2,%3}, [%4];\n"
        : "=r"(r[0]), "=r"(r[1]), "=r"(r[2]), "=r"(r[3]) : "r"(addr));
}
__device__ __forceinline__ void mma_bf16(float* c, const uint32_t* a, uint32_t b0, uint32_t b1) {
    asm volatile(
        "mma.sync.aligned.m16n8k16.row.col.f32.bf16.bf16.f32 "
        "{%0,%1,%2,%3}, {%4,%5,%6,%7}, {%8,%9}, {%0,%1,%2,%3};\n"
        : "+f"(c[0]), "+f"(c[1]), "+f"(c[2]), "+f"(c[3])
        : "r"(a[0]), "r"(a[1]), "r"(a[2]), "r"(a[3]), "r"(b0), "r"(b1));
}
__device__ __forceinline__ float gelu_erf(float x) {
    return 0.5f * x * (1.0f + erff(x * 0.70710678118654752f));
}
__device__ __forceinline__ uint32_t pack_bf2(float a, float b) {
    __nv_bfloat162 h; h.x = __float2bfloat16(a); h.y = __float2bfloat16(b);
    return *reinterpret_cast<uint32_t*>(&h);
}

// ======================= HMMA GEMM: C[M,N] = A[M,K] @ B[N,K]^T =======================
// A row-major [M][K] (stride lda), B K-major [N][K] (stride ldb).
// Tile 128x256xBK64, 512 threads, warp tile 64x32 (2x8 warp grid).
// SPLIT: 3-product hi/lo bf16 emulation of fp32.
// EPI: 0 (+bias?)->f32 | 1 +bias->hi/lo bf16 | 2 +bias,gelu->hi/lo | 3 +bias->bf16
//      4 exp(acc*scale)->bf16 + per-tile rowsum partials
template<int EPI, bool SPLIT>
__global__ void __launch_bounds__(512, 1) gemm_hmma(
    const __nv_bfloat16* __restrict__ Ah, const __nv_bfloat16* __restrict__ Al,
    const __nv_bfloat16* __restrict__ Bh, const __nv_bfloat16* __restrict__ Bl,
    const float* __restrict__ bias,
    float* __restrict__ outF, __nv_bfloat16* __restrict__ outHi, __nv_bfloat16* __restrict__ outLo,
    float* __restrict__ prs, float scale,
    int K, int lda, int ldb, int ldc, size_t zstride)
{
    constexpr int SSTRIDE = SPLIT ? 98304 : 49152;   // [A 16K][B 32K] (+[Al][Bl] at +49152)
    extern __shared__ char smem[];
    const uint32_t sb = (uint32_t)__cvta_generic_to_shared(smem);
    const int tid = threadIdx.x;
    const int lane = tid & 31, wid = tid >> 5;
    const int wm = wid & 1, wn = wid >> 1;           // 2x8 warp grid
    const int m0 = blockIdx.x * BM;
    const int n0 = blockIdx.y * BN;
    const size_t kz = (size_t)blockIdx.z * K;
    outF += (size_t)blockIdx.z * zstride;

    float acc[4][4][4];
    #pragma unroll
    for (int i = 0; i < 4; i++)
        #pragma unroll
        for (int j = 0; j < 4; j++)
            #pragma unroll
            for (int q = 0; q < 4; q++) acc[i][j][q] = 0.f;

    const int nkb = K / BK;

    auto LOAD = [&](int st, int kb) {
        const uint32_t base = sb + st * SSTRIDE;
        const size_t kg = kz + (size_t)kb * BK;
        #pragma unroll
        for (int i = 0; i < 2; i++) {               // A: 128 rows x 8 chunks
            int id = tid + i * 512;
            int row = id >> 3, c = id & 7;
            uint32_t so = base + row * 128 + ((c ^ (row & 7)) << 4);
            const __nv_bfloat16* gp = Ah + (size_t)(m0 + row) * lda + kg + c * 8;
            cpasync16(so, gp);
            if (SPLIT) cpasync16(so + 49152, Al + (size_t)(m0 + row) * lda + kg + c * 8);
        }
        #pragma unroll
        for (int i = 0; i < 4; i++) {               // B: 256 rows x 8 chunks
            int id = tid + i * 512;
            int row = id >> 3, c = id & 7;
            uint32_t so = base + 16384 + row * 128 + ((c ^ (row & 7)) << 4);
            cpasync16(so, Bh + (size_t)(n0 + row) * ldb + kg + c * 8);
            if (SPLIT) cpasync16(so + 49152, Bl + (size_t)(n0 + row) * ldb + kg + c * 8);
        }
        asm volatile("cp.async.commit_group;" ::);
    };

    const int amat = lane >> 3;
    const int arow_l = (amat & 1) * 8 + (lane & 7);   // A lane row within m16
    const int achv   = amat >> 1;                      // A lane k-chunk offset
    const int brow_l = (amat >> 1) * 8 + (lane & 7);   // B lane row within n16
    const int bchv   = amat & 1;

    auto COMPUTE = [&](int st) {
        const uint32_t ab = sb + st * SSTRIDE;
        const uint32_t bb = ab + 16384;
        #pragma unroll
        for (int t = 0; t < 4; t++) {
            uint32_t ah[4][4], bh[2][4];
            #pragma unroll
            for (int mi = 0; mi < 4; mi++) {
                int row = wm * 64 + mi * 16 + arow_l;
                int ch = 2 * t + achv;
                ldsm4(ah[mi], ab + row * 128 + ((ch ^ (row & 7)) << 4));
            }
            #pragma unroll
            for (int nb = 0; nb < 2; nb++) {
                int row = wn * 32 + nb * 16 + brow_l;
                int ch = 2 * t + bchv;
                ldsm4(bh[nb], bb + row * 128 + ((ch ^ (row & 7)) << 4));
            }
            if (!SPLIT) {
                #pragma unroll
                for (int mi = 0; mi < 4; mi++)
                    #pragma unroll
                    for (int ni = 0; ni < 4; ni++)
                        mma_bf16(acc[mi][ni], ah[mi],
                                 bh[ni >> 1][(ni & 1) * 2], bh[ni >> 1][(ni & 1) * 2 + 1]);
            } else {
                uint32_t al[4][4], bl[2][4];
                #pragma unroll
                for (int mi = 0; mi < 4; mi++) {
                    int row = wm * 64 + mi * 16 + arow_l;
                    int ch = 2 * t + achv;
                    ldsm4(al[mi], ab + 49152 + row * 128 + ((ch ^ (row & 7)) << 4));
                }
                #pragma unroll
                for (int nb = 0; nb < 2; nb++) {
                    int row = wn * 32 + nb * 16 + brow_l;
                    int ch = 2 * t + bchv;
                    ldsm4(bl[nb], bb + 49152 + row * 128 + ((ch ^ (row & 7)) << 4));
                }
                #pragma unroll
                for (int mi = 0; mi < 4; mi++)
                    #pragma unroll
                    for (int ni = 0; ni < 4; ni++) {
                        uint32_t b0 = bh[ni >> 1][(ni & 1) * 2], b1 = bh[ni >> 1][(ni & 1) * 2 + 1];
                        uint32_t c0 = bl[ni >> 1][(ni & 1) * 2], c1 = bl[ni >> 1][(ni & 1) * 2 + 1];
                        mma_bf16(acc[mi][ni], ah[mi], b0, b1);
                        mma_bf16(acc[mi][ni], al[mi], b0, b1);
                        mma_bf16(acc[mi][ni], ah[mi], c0, c1);
                    }
            }
        }
    };

    if (!SPLIT) {
        LOAD(0, 0);
        if (nkb > 1) LOAD(1, 1);
        for (int kb = 0; kb < nkb; kb++) {
            if (kb + 2 < nkb) {
                LOAD((kb + 2) % 3, kb + 2);
                asm volatile("cp.async.wait_group 2;" ::: "memory");
            } else if (kb + 1 < nkb) {
                asm volatile("cp.async.wait_group 1;" ::: "memory");
            } else {
                asm volatile("cp.async.wait_group 0;" ::: "memory");
            }
            __syncthreads();
            COMPUTE(kb % 3);
            __syncthreads();
        }
    } else {
        LOAD(0, 0);
        for (int kb = 0; kb < nkb; kb++) {
            if (kb + 1 < nkb) {
                LOAD((kb + 1) & 1, kb + 1);
                asm volatile("cp.async.wait_group 1;" ::: "memory");
            } else {
                asm volatile("cp.async.wait_group 0;" ::: "memory");
            }
            __syncthreads();
            COMPUTE(kb & 1);
            __syncthreads();
        }
    }

    // -------- epilogue: stage full 128x256 fp32 tile in SMEM, then coalesced out --------
    float* smf = reinterpret_cast<float*>(smem);
    float* redbuf = smf + 128 * 258;                 // 512 floats for EPI4 rowsum
    #pragma unroll
    for (int mi = 0; mi < 4; mi++) {
        #pragma unroll
        for (int ni = 0; ni < 4; ni++) {
            int r = wm * 64 + mi * 16 + (lane >> 2);
            int cc = wn * 32 + ni * 8 + (lane & 3) * 2;
            smf[r * 258 + cc]           = acc[mi][ni][0];
            smf[r * 258 + cc + 1]       = acc[mi][ni][1];
            smf[(r + 8) * 258 + cc]     = acc[mi][ni][2];
            smf[(r + 8) * 258 + cc + 1] = acc[mi][ni][3];
        }
    }
    __syncthreads();

    {
        const int r = tid & 127, sg = tid >> 7;      // 4 threads/row, 64 cols each
        const float* srow = smf + r * 258 + sg * 64;
        const int colbase = n0 + sg * 64;
        const int rowg = m0 + r;
        float v[64];
        float rsum = 0.f;
        #pragma unroll
        for (int j = 0; j < 64; j++) {
            float x = srow[j];
            if ((EPI >= 1 && EPI <= 3) || (EPI == 0 && bias != nullptr))
                x += __ldg(bias + colbase + j);
            if (EPI == 2) x = gelu_erf(x);
            if (EPI == 4) {
                x = __expf(x * scale);
                x = __bfloat162float(__float2bfloat16(x));   // match stored P exactly
                rsum += x;
            }
            v[j] = x;
        }
        if (EPI == 4) redbuf[sg * 128 + r] = rsum;

        const size_t gb = (size_t)rowg * ldc + colbase;
        if (EPI == 0) {
            #pragma unroll
            for (int j = 0; j < 64; j += 4) {
                float4 f = make_float4(v[j], v[j+1], v[j+2], v[j+3]);
                *reinterpret_cast<float4*>(outF + gb + j) = f;
            }
        } else if (EPI == 3 || EPI == 4) {
            #pragma unroll
            for (int j = 0; j < 64; j += 8) {
                uint4 u;
                u.x = pack_bf2(v[j+0], v[j+1]); u.y = pack_bf2(v[j+2], v[j+3]);
                u.z = pack_bf2(v[j+4], v[j+5]); u.w = pack_bf2(v[j+6], v[j+7]);
                *reinterpret_cast<uint4*>(outHi + gb + j) = u;
            }
        } else {
            #pragma unroll
            for (int j = 0; j < 64; j += 8) {
                float lo[8];
                #pragma unroll
                for (int q = 0; q < 8; q++) {
                    __nv_bfloat16 hb = __float2bfloat16(v[j + q]);
                    lo[q] = v[j + q] - __bfloat162float(hb);
                }
                uint4 uh, ul;
                uh.x = pack_bf2(v[j+0], v[j+1]); uh.y = pack_bf2(v[j+2], v[j+3]);
                uh.z = pack_bf2(v[j+4], v[j+5]); uh.w = pack_bf2(v[j+6], v[j+7]);
                ul.x = pack_bf2(lo[0], lo[1]);   ul.y = pack_bf2(lo[2], lo[3]);
                ul.z = pack_bf2(lo[4], lo[5]);   ul.w = pack_bf2(lo[6], lo[7]);
                *reinterpret_cast<uint4*>(outHi + gb + j) = uh;
                *reinterpret_cast<uint4*>(outLo + gb + j) = ul;
            }
        }
    }

    if (EPI == 4) {
        __syncthreads();
        if (tid < 128) {
            float s = redbuf[tid] + redbuf[128 + tid] + redbuf[256 + tid] + redbuf[384 + tid];
            prs[(size_t)(m0 + tid) * NT_LOGITS + blockIdx.y] = s;
        }
    }
}

// ---------------- conversion / reduction kernels ----------------
__global__ void k_split(const float* __restrict__ s, __nv_bfloat16* __restrict__ hi,
                        __nv_bfloat16* __restrict__ lo, int n)
{
    for (int i = blockIdx.x * blockDim.x + threadIdx.x; i < n; i += gridDim.x * blockDim.x) {
        float v = s[i];
        __nv_bfloat16 h = __float2bfloat16(v);
        hi[i] = h;
        lo[i] = __float2bfloat16(v - __bfloat162float(h));
    }
}
// src [K][N] f32 -> hi/lo [N][K] bf16 (transposed split: tcgen05-style [N][K] B operand)
__global__ void k_split_t(const float* __restrict__ src, __nv_bfloat16* __restrict__ hi,
                          __nv_bfloat16* __restrict__ lo, int K, int N)
{
    __shared__ float t[32][33];
    const int n0 = blockIdx.x << 5, k0 = blockIdx.y << 5;
    #pragma unroll
    for (int i = 0; i < 4; i++) {
        int r = threadIdx.y + i * 8;
        t[r][threadIdx.x] = src[(size_t)(k0 + r) * N + n0 + threadIdx.x];
    }
    __syncthreads();
    #pragma unroll
    for (int i = 0; i < 4; i++) {
        int c = threadIdx.y + i * 8;
        float v = t[threadIdx.x][c];
        __nv_bfloat16 h = __float2bfloat16(v);
        size_t o = (size_t)(n0 + c) * K + k0 + threadIdx.x;
        hi[o] = h;
        lo[o] = __float2bfloat16(v - __bfloat162float(h));
    }
}
__global__ void k_tobf16(const float* __restrict__ s, __nv_bfloat16* __restrict__ d, size_t n)
{
    for (size_t i = blockIdx.x * (size_t)blockDim.x + threadIdx.x; i < n;
         i += (size_t)gridDim.x * blockDim.x)
        d[i] = __float2bfloat16(s[i]);
}
// mem_values [MEM][HID] f32 -> g_MVT [HID][MEM] bf16
__global__ void k_transpose_bf16(const float* __restrict__ src, __nv_bfloat16* __restrict__ dst)
{
    __shared__ __nv_bfloat16 tile[32][33];
    const int r0 = blockIdx.y << 5;   // MEM base
    const int c0 = blockIdx.x << 5;   // HID base
    #pragma unroll
    for (int i = 0; i < 4; i++) {
        int r = threadIdx.y + i * 8;
        tile[r][threadIdx.x] = __float2bfloat16(src[(size_t)(r0 + r) * HID + c0 + threadIdx.x]);
    }
    __syncthreads();
    #pragma unroll
    for (int i = 0; i < 4; i++) {
        int c = threadIdx.y + i * 8;
        dst[(size_t)(c0 + c) * MEM + r0 + threadIdx.x] = tile[threadIdx.x][c];
    }
}
// rowsum from per-tile partials: one warp per row (deterministic)
__global__ void k_rsreduce(const float* __restrict__ prs, float* __restrict__ rs)
{
    const int row = blockIdx.x * 8 + (threadIdx.x >> 5);
    const int lane = threadIdx.x & 31;
    float s = 0.f;
    #pragma unroll
    for (int j = 0; j < NT_LOGITS / 32; j++)
        s += prs[(size_t)row * NT_LOGITS + lane + j * 32];
    #pragma unroll
    for (int o = 16; o > 0; o >>= 1) s += __shfl_xor_sync(0xffffffffu, s, o);
    if (lane == 0) rs[row] = s;
}
// combine split-K partials, scale by 1/rowsum, write retrieved into combined[:, HID:]
__global__ void k_combine(const float* __restrict__ part, const float* __restrict__ rs,
                          __nv_bfloat16* __restrict__ ch, __nv_bfloat16* __restrict__ cl)
{
    const int i = blockIdx.x * 256 + threadIdx.x;   // float4 index
    const int e = i * 4;
    const int r = e >> 10;
    const int c = e & 1023;
    float4 a = make_float4(0.f, 0.f, 0.f, 0.f);
    #pragma unroll
    for (int s = 0; s < KSPLIT; s++) {
        const float4 v = *reinterpret_cast<const float4*>(part + (size_t)s * NQ * HID + e);
        a.x += v.x; a.y += v.y; a.z += v.z; a.w += v.w;
    }
    const float inv = 1.0f / rs[r];
    float v4[4] = {a.x * inv, a.y * inv, a.z * inv, a.w * inv};
    float lo[4];
    #pragma unroll
    for (int j = 0; j < 4; j++) {
        __nv_bfloat16 h = __float2bfloat16(v4[j]);
        lo[j] = v4[j] - __bfloat162float(h);
    }
    const size_t o = (size_t)r * (2 * HID) + HID + c;
    uint2 uh, ul;
    uh.x = pack_bf2(v4[0], v4[1]); uh.y = pack_bf2(v4[2], v4[3]);
    ul.x = pack_bf2(lo[0], lo[1]); ul.y = pack_bf2(lo[2], lo[3]);
    *reinterpret_cast<uint2*>(ch + o) = uh;
    *reinterpret_cast<uint2*>(cl + o) = ul;
}

// ---------------- launch ----------------
#define DEVPTR(name, sym, type) \
    type* name; { void* p_ = nullptr; cudaGetSymbolAddress(&p_, sym); name = (type*)p_; }

#define SMEM_NS 147456   // 3 stages x 48KB (epilogue needs 134144 <= this)
#define SMEM_SP 196608   // 2 stages x 96KB

extern "C" void kernel_launch(void* const* d_in, const int* in_sizes, int n_in,
                              void* d_out, int out_size)
{
    (void)in_sizes; (void)n_in; (void)out_size;
    const float* query = (const float*)d_in[0];
    const float* W_in  = (const float*)d_in[1];
    const float* b_in  = (const float*)d_in[2];
    const float* W_e1  = (const float*)d_in[3];
    const float* b_e1  = (const float*)d_in[4];
    const float* W_e2  = (const float*)d_in[5];
    const float* b_e2  = (const float*)d_in[6];
    const float* W_k   = (const float*)d_in[7];
    const float* b_k   = (const float*)d_in[8];
    const float* mem_keys   = (const float*)d_in[9];
    const float* mem_values = (const float*)d_in[10];
    const float* W_r1  = (const float*)d_in[11];
    const float* b_r1  = (const float*)d_in[12];
    const float* W_r2  = (const float*)d_in[13];
    const float* b_r2  = (const float*)d_in[14];
    float* out = (float*)d_out;

    DEVPTR(qh, g_qh, __nv_bfloat16)     DEVPTR(ql, g_ql, __nv_bfloat16)
    DEVPTR(Winh, g_Winh, __nv_bfloat16) DEVPTR(Winl, g_Winl, __nv_bfloat16)
    DEVPTR(We1h, g_We1h, __nv_bfloat16) DEVPTR(We1l, g_We1l, __nv_bfloat16)
    DEVPTR(We2h, g_We2h, __nv_bfloat16) DEVPTR(We2l, g_We2l, __nv_bfloat16)
    DEVPTR(Wkh, g_Wkh, __nv_bfloat16)   DEVPTR(Wkl, g_Wkl, __nv_bfloat16)
    DEVPTR(Wr1h, g_Wr1h, __nv_bfloat16) DEVPTR(Wr1l, g_Wr1l, __nv_bfloat16)
    DEVPTR(Wr2h, g_Wr2h, __nv_bfloat16) DEVPTR(Wr2l, g_Wr2l, __nv_bfloat16)
    DEVPTR(MK, g_MK, __nv_bfloat16)     DEVPTR(MVT, g_MVT, __nv_bfloat16)
    DEVPTR(xh, g_xh, __nv_bfloat16)     DEVPTR(xl, g_xl, __nv_bfloat16)
    DEVPTR(hh, g_hh, __nv_bfloat16)     DEVPTR(hl, g_hl, __nv_bfloat16)
    DEVPTR(ch, g_ch, __nv_bfloat16)     DEVPTR(cl, g_cl, __nv_bfloat16)
    DEVPTR(key, g_key, __nv_bfloat16)
    DEVPTR(P, g_P, __nv_bfloat16)
    DEVPTR(rh, g_rh, __nv_bfloat16)     DEVPTR(rl, g_rl, __nv_bfloat16)
    DEVPTR(part, g_part, float)
    DEVPTR(prs, g_prs, float)
    DEVPTR(rowsum, g_rowsum, float)

    cudaFuncSetAttribute(gemm_hmma<0,true>,  cudaFuncAttributeMaxDynamicSharedMemorySize, SMEM_SP);
    cudaFuncSetAttribute(gemm_hmma<1,true>,  cudaFuncAttributeMaxDynamicSharedMemorySize, SMEM_SP);
    cudaFuncSetAttribute(gemm_hmma<2,true>,  cudaFuncAttributeMaxDynamicSharedMemorySize, SMEM_SP);
    cudaFuncSetAttribute(gemm_hmma<3,true>,  cudaFuncAttributeMaxDynamicSharedMemorySize, SMEM_SP);
    cudaFuncSetAttribute(gemm_hmma<4,false>, cudaFuncAttributeMaxDynamicSharedMemorySize, SMEM_NS);
    cudaFuncSetAttribute(gemm_hmma<0,false>, cudaFuncAttributeMaxDynamicSharedMemorySize, SMEM_NS);

    // ---- conversions ----
    k_split<<<(NQ*EMB + 255) / 256, 256>>>(query, qh, ql, NQ*EMB);
    k_split_t<<<dim3(HID/32,  EMB/32),   dim3(32,8)>>>(W_in, Winh, Winl, EMB,   HID);
    k_split_t<<<dim3(2*HID/32, HID/32),  dim3(32,8)>>>(W_e1, We1h, We1l, HID,   2*HID);
    k_split_t<<<dim3(HID/32,  2*HID/32), dim3(32,8)>>>(W_e2, We2h, We2l, 2*HID, HID);
    k_split_t<<<dim3(HID/32,  HID/32),   dim3(32,8)>>>(W_k,  Wkh,  Wkl,  HID,   HID);
    k_split_t<<<dim3(2*HID/32, 2*HID/32),dim3(32,8)>>>(W_r1, Wr1h, Wr1l, 2*HID, 2*HID);
    k_split_t<<<dim3(EMB/32,  2*HID/32), dim3(32,8)>>>(W_r2, Wr2h, Wr2l, 2*HID, EMB);
    k_tobf16<<<8192, 256>>>(mem_keys, MK, (size_t)MEM * HID);
    k_transpose_bf16<<<dim3(HID/32, MEM/32), dim3(32, 8)>>>(mem_values, MVT);

    // ---- GEMM chain (all B operands are [N][K]) ----
    // x = query @ W_in + b_in
    gemm_hmma<1,true><<<dim3(NQ/BM, HID/BN), 512, SMEM_SP>>>(
        qh, ql, Winh, Winl, b_in, nullptr, xh, xl, nullptr, 0.f, EMB, EMB, EMB, HID, 0);
    // h = gelu(x @ W_e1 + b_e1)
    gemm_hmma<2,true><<<dim3(NQ/BM, 2*HID/BN), 512, SMEM_SP>>>(
        xh, xl, We1h, We1l, b_e1, nullptr, hh, hl, nullptr, 0.f, HID, HID, HID, 2*HID, 0);
    // encoded = h @ W_e2 + b_e2 -> combined[:, 0:HID]
    gemm_hmma<1,true><<<dim3(NQ/BM, HID/BN), 512, SMEM_SP>>>(
        hh, hl, We2h, We2l, b_e2, nullptr, ch, cl, nullptr, 0.f,
        2*HID, 2*HID, 2*HID, 2*HID, 0);
    // key = encoded @ W_k + b_k  (A = combined left half)
    gemm_hmma<3,true><<<dim3(NQ/BM, HID/BN), 512, SMEM_SP>>>(
        ch, cl, Wkh, Wkl, b_k, nullptr, key, nullptr, nullptr, 0.f,
        HID, 2*HID, HID, HID, 0);
    // P = exp((key @ mem_keys^T) / 32), fused per-tile rowsum partials
    gemm_hmma<4,false><<<dim3(NQ/BM, MEM/BN), 512, SMEM_NS>>>(
        key, nullptr, MK, nullptr, nullptr, nullptr, P, nullptr, prs, 0.03125f,
        HID, HID, HID, MEM, 0);
    // rowsum (deterministic reduce of partials)
    k_rsreduce<<<NQ/8, 256>>>(prs, rowsum);
    // retrieved partials: deterministic split-K over MEM
    gemm_hmma<0,false><<<dim3(NQ/BM, HID/BN, KSPLIT), 512, SMEM_NS>>>(
        P, nullptr, MVT, nullptr, nullptr, part, nullptr, nullptr, nullptr, 0.f,
        MEM/KSPLIT, MEM, MEM, HID, (size_t)NQ * HID);
    // combine + 1/rowsum -> combined[:, HID:2*HID]
    k_combine<<<NQ*HID/4/256, 256>>>(part, rowsum, ch, cl);
    // r = gelu(combined @ W_r1 + b_r1)
    gemm_hmma<2,true><<<dim3(NQ/BM, 2*HID/BN), 512, SMEM_SP>>>(
        ch, cl, Wr1h, Wr1l, b_r1, nullptr, rh, rl, nullptr, 0.f,
        2*HID, 2*HID, 2*HID, 2*HID, 0);
    // result = r @ W_r2 + b_r2 -> fp32 out
    gemm_hmma<0,true><<<dim3(NQ/BM, EMB/BN), 512, SMEM_SP>>>(
        rh, rl, Wr2h, Wr2l, b_r2, out, nullptr, nullptr, nullptr, 0.f,
        2*HID, 2*HID, 2*HID, EMB, 0);
}

// round 5
// speedup vs baseline: 1.4810x; 1.0317x over previous
#include <cuda_runtime.h>
#include <cuda_bf16.h>
#include <cstdint>
#include <cstddef>

#define NQ  4096
#define EMB 768
#define HID 1024
#define MEM 65536
#define KSPLIT 4
#define BM 128
#define BN 256
#define NT_LOGITS (MEM / BN)   // 256 n-tiles in logits GEMM

// ---------------- static device scratch ----------------
__device__ __nv_bfloat16 g_qh[NQ*EMB],        g_ql[NQ*EMB];
__device__ __nv_bfloat16 g_Winh[HID*EMB],     g_Winl[HID*EMB];      // weights transposed: [N][K]
__device__ __nv_bfloat16 g_We1h[2*HID*HID],   g_We1l[2*HID*HID];
__device__ __nv_bfloat16 g_We2h[HID*2*HID],   g_We2l[HID*2*HID];
__device__ __nv_bfloat16 g_Wkh[HID*HID],      g_Wkl[HID*HID];
__device__ __nv_bfloat16 g_Wr1h[2*HID*2*HID], g_Wr1l[2*HID*2*HID];
__device__ __nv_bfloat16 g_Wr2h[EMB*2*HID],   g_Wr2l[EMB*2*HID];
__device__ __nv_bfloat16 g_MK [(size_t)MEM*HID];    // mem_keys bf16 [MEM][HID]  (= [N][K])
__device__ __nv_bfloat16 g_MVT[(size_t)HID*MEM];    // mem_values^T [HID][MEM]   (= [N][K])
__device__ __nv_bfloat16 g_xh[NQ*HID],   g_xl[NQ*HID];
__device__ __nv_bfloat16 g_hh[NQ*2*HID], g_hl[NQ*2*HID];
__device__ __nv_bfloat16 g_ch[NQ*2*HID], g_cl[NQ*2*HID];   // combined = [encoded | retrieved]
__device__ __nv_bfloat16 g_key[NQ*HID];
__device__ __nv_bfloat16 g_P[(size_t)NQ*MEM];              // exp(logits/32) bf16
__device__ __nv_bfloat16 g_rh[NQ*2*HID], g_rl[NQ*2*HID];
__device__ float         g_part[(size_t)KSPLIT*NQ*HID];    // split-K partials
__device__ float         g_prs[(size_t)NQ*NT_LOGITS];      // per-tile rowsum partials
__device__ float         g_rowsum[NQ];

// ---------------- helpers ----------------
__device__ __forceinline__ void cpasync16(uint32_t saddr, const void* g) {
    asm volatile("cp.async.cg.shared.global [%0], [%1], 16;\n" :: "r"(saddr), "l"(g));
}
__device__ __forceinline__ void ldsm4(uint32_t* r, uint32_t addr) {
    asm volatile("ldmatrix.sync.aligned.m8n8.x4.shared.b16 {%0,%1,%2,%3}, [%4];\n"
        : "=r"(r[0]), "=r"(r[1]), "=r"(r[2]), "=r"(r[3]) : "r"(addr));
}
__device__ __forceinline__ void mma_bf16(float* c, const uint32_t* a, uint32_t b0, uint32_t b1) {
    asm volatile(
        "mma.sync.aligned.m16n8k16.row.col.f32.bf16.bf16.f32 "
        "{%0,%1,%2,%3}, {%4,%5,%6,%7}, {%8,%9}, {%0,%1,%2,%3};\n"
        : "+f"(c[0]), "+f"(c[1]), "+f"(c[2]), "+f"(c[3])
        : "r"(a[0]), "r"(a[1]), "r"(a[2]), "r"(a[3]), "r"(b0), "r"(b1));
}
__device__ __forceinline__ float gelu_erf(float x) {
    return 0.5f * x * (1.0f + erff(x * 0.70710678118654752f));
}
__device__ __forceinline__ uint32_t pack_bf2(float a, float b) {
    __nv_bfloat162 h; h.x = __float2bfloat16(a); h.y = __float2bfloat16(b);
    return *reinterpret_cast<uint32_t*>(&h);
}

// ======================= HMMA GEMM: C[M,N] = A[M,K] @ B[N,K]^T =======================
// A row-major [M][K] (stride lda), B K-major [N][K] (stride ldb).
// Tile 128x256, 512 threads, warp tile 64x32 (2x8 warp grid).
// Non-split: BK=64, 3 stages. Split (3-product hi/lo bf16): BK=32, 4 stages.
// Stage layout (48KB both): non-split [A 16K][B 32K]; split [Ah 8K][Bh 16K][Al 8K][Bl 16K].
// EPI: 0 (+bias?)->f32 | 1 +bias->hi/lo bf16 | 2 +bias,gelu->hi/lo | 3 +bias->bf16
//      4 exp(acc*scale)->bf16 + per-tile rowsum partials
// SWAP: n-tile on blockIdx.x (fastest) -- for A-operand-dominant GEMMs.
template<int EPI, bool SPLIT, bool SWAP>
__global__ void __launch_bounds__(512, 1) gemm_hmma(
    const __nv_bfloat16* __restrict__ Ah, const __nv_bfloat16* __restrict__ Al,
    const __nv_bfloat16* __restrict__ Bh, const __nv_bfloat16* __restrict__ Bl,
    const float* __restrict__ bias,
    float* __restrict__ outF, __nv_bfloat16* __restrict__ outHi, __nv_bfloat16* __restrict__ outLo,
    float* __restrict__ prs, float scale,
    int K, int lda, int ldb, int ldc, size_t zstride)
{
    constexpr int BK  = SPLIT ? 32 : 64;
    constexpr int NST = SPLIT ? 4 : 3;
    constexpr int PRE = NST - 1;
    constexpr int SST = 49152;
    extern __shared__ char smem[];
    const uint32_t sb = (uint32_t)__cvta_generic_to_shared(smem);
    const int tid = threadIdx.x;
    const int lane = tid & 31, wid = tid >> 5;
    const int wm = wid & 1, wn = wid >> 1;           // 2x8 warp grid
    const int m0 = (SWAP ? blockIdx.y : blockIdx.x) * BM;
    const int n0 = (SWAP ? blockIdx.x : blockIdx.y) * BN;
    const int ntile = SWAP ? blockIdx.x : blockIdx.y;
    const size_t kz = (size_t)blockIdx.z * K;
    outF += (size_t)blockIdx.z * zstride;

    float acc[4][4][4];
    #pragma unroll
    for (int i = 0; i < 4; i++)
        #pragma unroll
        for (int j = 0; j < 4; j++)
            #pragma unroll
            for (int q = 0; q < 4; q++) acc[i][j][q] = 0.f;

    const int nkb = K / BK;

    auto LOAD = [&](int st, int kb) {
        const uint32_t base = sb + st * SST;
        const size_t kg = kz + (size_t)kb * BK;
        if (!SPLIT) {
            #pragma unroll
            for (int i = 0; i < 2; i++) {           // A: 128 rows x 8 chunks
                int id = tid + i * 512;
                int row = id >> 3, c = id & 7;
                uint32_t so = base + row * 128 + ((c ^ (row & 7)) << 4);
                cpasync16(so, Ah + (size_t)(m0 + row) * lda + kg + c * 8);
            }
            #pragma unroll
            for (int i = 0; i < 4; i++) {           // B: 256 rows x 8 chunks
                int id = tid + i * 512;
                int row = id >> 3, c = id & 7;
                uint32_t so = base + 16384 + row * 128 + ((c ^ (row & 7)) << 4);
                cpasync16(so, Bh + (size_t)(n0 + row) * ldb + kg + c * 8);
            }
        } else {
            {                                        // A: 128 rows x 4 chunks (1/thread)
                int row = tid >> 2, c = tid & 3;
                uint32_t so = base + row * 64 + ((c ^ ((row >> 1) & 3)) << 4);
                const size_t go = (size_t)(m0 + row) * lda + kg + c * 8;
                cpasync16(so, Ah + go);
                cpasync16(so + 24576, Al + go);
            }
            #pragma unroll
            for (int i = 0; i < 2; i++) {           // B: 256 rows x 4 chunks (2/thread)
                int id = tid + i * 512;
                int row = id >> 2, c = id & 3;
                uint32_t so = base + 8192 + row * 64 + ((c ^ ((row >> 1) & 3)) << 4);
                const size_t go = (size_t)(n0 + row) * ldb + kg + c * 8;
                cpasync16(so, Bh + go);
                cpasync16(so + 24576, Bl + go);
            }
        }
        asm volatile("cp.async.commit_group;" ::);
    };

    const int amat = lane >> 3;
    const int arow_l = (amat & 1) * 8 + (lane & 7);   // A lane row within m16
    const int achv   = amat >> 1;                      // A lane k-chunk offset
    const int brow_l = (amat >> 1) * 8 + (lane & 7);   // B lane row within n16
    const int bchv   = amat & 1;

    auto COMPUTE = [&](int st) {
        const uint32_t ab = sb + st * SST;
        if (!SPLIT) {
            const uint32_t bb = ab + 16384;
            #pragma unroll
            for (int t = 0; t < 4; t++) {
                uint32_t a[4][4], b[2][4];
                #pragma unroll
                for (int mi = 0; mi < 4; mi++) {
                    int row = wm * 64 + mi * 16 + arow_l;
                    int ch = 2 * t + achv;
                    ldsm4(a[mi], ab + row * 128 + ((ch ^ (row & 7)) << 4));
                }
                #pragma unroll
                for (int nb = 0; nb < 2; nb++) {
                    int row = wn * 32 + nb * 16 + brow_l;
                    int ch = 2 * t + bchv;
                    ldsm4(b[nb], bb + row * 128 + ((ch ^ (row & 7)) << 4));
                }
                #pragma unroll
                for (int mi = 0; mi < 4; mi++)
                    #pragma unroll
                    for (int ni = 0; ni < 4; ni++)
                        mma_bf16(acc[mi][ni], a[mi],
                                 b[ni >> 1][(ni & 1) * 2], b[ni >> 1][(ni & 1) * 2 + 1]);
            }
        } else {
            const uint32_t bb = ab + 8192;
            #pragma unroll
            for (int t = 0; t < 2; t++) {
                uint32_t ah[4][4], bh[2][4];
                #pragma unroll
                for (int mi = 0; mi < 4; mi++) {
                    int row = wm * 64 + mi * 16 + arow_l;
                    int ch = 2 * t + achv;
                    ldsm4(ah[mi], ab + row * 64 + ((ch ^ ((row >> 1) & 3)) << 4));
                }
                #pragma unroll
                for (int nb = 0; nb < 2; nb++) {
                    int row = wn * 32 + nb * 16 + brow_l;
                    int ch = 2 * t + bchv;
                    ldsm4(bh[nb], bb + row * 64 + ((ch ^ ((row >> 1) & 3)) << 4));
                }
                #pragma unroll
                for (int mi = 0; mi < 4; mi++)
                    #pragma unroll
                    for (int ni = 0; ni < 4; ni++)
                        mma_bf16(acc[mi][ni], ah[mi],
                                 bh[ni >> 1][(ni & 1) * 2], bh[ni >> 1][(ni & 1) * 2 + 1]);
                {   // Al x Bh  (al lives only in this block)
                    uint32_t al[4][4];
                    #pragma unroll
                    for (int mi = 0; mi < 4; mi++) {
                        int row = wm * 64 + mi * 16 + arow_l;
                        int ch = 2 * t + achv;
                        ldsm4(al[mi], ab + 24576 + row * 64 + ((ch ^ ((row >> 1) & 3)) << 4));
                    }
                    #pragma unroll
                    for (int mi = 0; mi < 4; mi++)
                        #pragma unroll
                        for (int ni = 0; ni < 4; ni++)
                            mma_bf16(acc[mi][ni], al[mi],
                                     bh[ni >> 1][(ni & 1) * 2], bh[ni >> 1][(ni & 1) * 2 + 1]);
                }
                {   // Ah x Bl
                    uint32_t bl[2][4];
                    #pragma unroll
                    for (int nb = 0; nb < 2; nb++) {
                        int row = wn * 32 + nb * 16 + brow_l;
                        int ch = 2 * t + bchv;
                        ldsm4(bl[nb], bb + 24576 + row * 64 + ((ch ^ ((row >> 1) & 3)) << 4));
                    }
                    #pragma unroll
                    for (int mi = 0; mi < 4; mi++)
                        #pragma unroll
                        for (int ni = 0; ni < 4; ni++)
                            mma_bf16(acc[mi][ni], ah[mi],
                                     bl[ni >> 1][(ni & 1) * 2], bl[ni >> 1][(ni & 1) * 2 + 1]);
                }
            }
        }
    };

    // ---- single-barrier pipelined mainloop ----
    #pragma unroll
    for (int i = 0; i < PRE; i++) LOAD(i, i);

    for (int kb = 0; kb < nkb; kb++) {
        const int pend = (nkb - kb < PRE) ? (nkb - kb) : PRE;
        if (PRE == 3) {
            if (pend == 3)      asm volatile("cp.async.wait_group 2;" ::: "memory");
            else if (pend == 2) asm volatile("cp.async.wait_group 1;" ::: "memory");
            else                asm volatile("cp.async.wait_group 0;" ::: "memory");
        } else {
            if (pend == 2)      asm volatile("cp.async.wait_group 1;" ::: "memory");
            else                asm volatile("cp.async.wait_group 0;" ::: "memory");
        }
        __syncthreads();
        COMPUTE(kb % NST);
        if (kb + PRE < nkb) LOAD((kb + PRE) % NST, kb + PRE);
    }
    __syncthreads();   // protect SMEM reuse by epilogue

    // -------- epilogue: stage full 128x256 fp32 tile in SMEM, then coalesced out --------
    float* smf = reinterpret_cast<float*>(smem);
    float* redbuf = smf + 128 * 258;                 // 512 floats for EPI4 rowsum
    #pragma unroll
    for (int mi = 0; mi < 4; mi++) {
        #pragma unroll
        for (int ni = 0; ni < 4; ni++) {
            int r = wm * 64 + mi * 16 + (lane >> 2);
            int cc = wn * 32 + ni * 8 + (lane & 3) * 2;
            smf[r * 258 + cc]           = acc[mi][ni][0];
            smf[r * 258 + cc + 1]       = acc[mi][ni][1];
            smf[(r + 8) * 258 + cc]     = acc[mi][ni][2];
            smf[(r + 8) * 258 + cc + 1] = acc[mi][ni][3];
        }
    }
    __syncthreads();

    {
        const int r = tid & 127, sg = tid >> 7;      // 4 threads/row, 64 cols each
        const float* srow = smf + r * 258 + sg * 64;
        const int colbase = n0 + sg * 64;
        const int rowg = m0 + r;
        float v[64];
        float rsum = 0.f;
        #pragma unroll
        for (int j = 0; j < 64; j++) {
            float x = srow[j];
            if ((EPI >= 1 && EPI <= 3) || (EPI == 0 && bias != nullptr))
                x += __ldg(bias + colbase + j);
            if (EPI == 2) x = gelu_erf(x);
            if (EPI == 4) {
                x = __expf(x * scale);
                x = __bfloat162float(__float2bfloat16(x));   // match stored P exactly
                rsum += x;
            }
            v[j] = x;
        }
        if (EPI == 4) redbuf[sg * 128 + r] = rsum;

        const size_t gb = (size_t)rowg * ldc + colbase;
        if (EPI == 0) {
            #pragma unroll
            for (int j = 0; j < 64; j += 4) {
                float4 f = make_float4(v[j], v[j+1], v[j+2], v[j+3]);
                *reinterpret_cast<float4*>(outF + gb + j) = f;
            }
        } else if (EPI == 3 || EPI == 4) {
            #pragma unroll
            for (int j = 0; j < 64; j += 8) {
                uint4 u;
                u.x = pack_bf2(v[j+0], v[j+1]); u.y = pack_bf2(v[j+2], v[j+3]);
                u.z = pack_bf2(v[j+4], v[j+5]); u.w = pack_bf2(v[j+6], v[j+7]);
                *reinterpret_cast<uint4*>(outHi + gb + j) = u;
            }
        } else {
            #pragma unroll
            for (int j = 0; j < 64; j += 8) {
                float lo[8];
                #pragma unroll
                for (int q = 0; q < 8; q++) {
                    __nv_bfloat16 hb = __float2bfloat16(v[j + q]);
                    lo[q] = v[j + q] - __bfloat162float(hb);
                }
                uint4 uh, ul;
                uh.x = pack_bf2(v[j+0], v[j+1]); uh.y = pack_bf2(v[j+2], v[j+3]);
                uh.z = pack_bf2(v[j+4], v[j+5]); uh.w = pack_bf2(v[j+6], v[j+7]);
                ul.x = pack_bf2(lo[0], lo[1]);   ul.y = pack_bf2(lo[2], lo[3]);
                ul.z = pack_bf2(lo[4], lo[5]);   ul.w = pack_bf2(lo[6], lo[7]);
                *reinterpret_cast<uint4*>(outHi + gb + j) = uh;
                *reinterpret_cast<uint4*>(outLo + gb + j) = ul;
            }
        }
    }

    if (EPI == 4) {
        __syncthreads();
        if (tid < 128) {
            float s = redbuf[tid] + redbuf[128 + tid] + redbuf[256 + tid] + redbuf[384 + tid];
            prs[(size_t)(m0 + tid) * NT_LOGITS + ntile] = s;
        }
    }
}

// ---------------- conversion / reduction kernels ----------------
__global__ void k_split(const float* __restrict__ s, __nv_bfloat16* __restrict__ hi,
                        __nv_bfloat16* __restrict__ lo, int n)
{
    for (int i = blockIdx.x * blockDim.x + threadIdx.x; i < n; i += gridDim.x * blockDim.x) {
        float v = s[i];
        __nv_bfloat16 h = __float2bfloat16(v);
        hi[i] = h;
        lo[i] = __float2bfloat16(v - __bfloat162float(h));
    }
}
// src [K][N] f32 -> hi/lo [N][K] bf16 (transposed split for [N][K] B operand)
__global__ void k_split_t(const float* __restrict__ src, __nv_bfloat16* __restrict__ hi,
                          __nv_bfloat16* __restrict__ lo, int K, int N)
{
    __shared__ float t[32][33];
    const int n0 = blockIdx.x << 5, k0 = blockIdx.y << 5;
    #pragma unroll
    for (int i = 0; i < 4; i++) {
        int r = threadIdx.y + i * 8;
        t[r][threadIdx.x] = src[(size_t)(k0 + r) * N + n0 + threadIdx.x];
    }
    __syncthreads();
    #pragma unroll
    for (int i = 0; i < 4; i++) {
        int c = threadIdx.y + i * 8;
        float v = t[threadIdx.x][c];
        __nv_bfloat16 h = __float2bfloat16(v);
        size_t o = (size_t)(n0 + c) * K + k0 + threadIdx.x;
        hi[o] = h;
        lo[o] = __float2bfloat16(v - __bfloat162float(h));
    }
}
__global__ void k_tobf16(const float* __restrict__ s, __nv_bfloat16* __restrict__ d, size_t n)
{
    for (size_t i = blockIdx.x * (size_t)blockDim.x + threadIdx.x; i < n;
         i += (size_t)gridDim.x * blockDim.x)
        d[i] = __float2bfloat16(s[i]);
}
// mem_values [MEM][HID] f32 -> g_MVT [HID][MEM] bf16
__global__ void k_transpose_bf16(const float* __restrict__ src, __nv_bfloat16* __restrict__ dst)
{
    __shared__ __nv_bfloat16 tile[32][33];
    const int r0 = blockIdx.y << 5;   // MEM base
    const int c0 = blockIdx.x << 5;   // HID base
    #pragma unroll
    for (int i = 0; i < 4; i++) {
        int r = threadIdx.y + i * 8;
        tile[r][threadIdx.x] = __float2bfloat16(src[(size_t)(r0 + r) * HID + c0 + threadIdx.x]);
    }
    __syncthreads();
    #pragma unroll
    for (int i = 0; i < 4; i++) {
        int c = threadIdx.y + i * 8;
        dst[(size_t)(c0 + c) * MEM + r0 + threadIdx.x] = tile[threadIdx.x][c];
    }
}
// rowsum from per-tile partials: one warp per row (deterministic)
__global__ void k_rsreduce(const float* __restrict__ prs, float* __restrict__ rs)
{
    const int row = blockIdx.x * 8 + (threadIdx.x >> 5);
    const int lane = threadIdx.x & 31;
    float s = 0.f;
    #pragma unroll
    for (int j = 0; j < NT_LOGITS / 32; j++)
        s += prs[(size_t)row * NT_LOGITS + lane + j * 32];
    #pragma unroll
    for (int o = 16; o > 0; o >>= 1) s += __shfl_xor_sync(0xffffffffu, s, o);
    if (lane == 0) rs[row] = s;
}
// combine split-K partials, scale by 1/rowsum, write retrieved into combined[:, HID:]
__global__ void k_combine(const float* __restrict__ part, const float* __restrict__ rs,
                          __nv_bfloat16* __restrict__ ch, __nv_bfloat16* __restrict__ cl)
{
    const int i = blockIdx.x * 256 + threadIdx.x;   // float4 index
    const int e = i * 4;
    const int r = e >> 10;
    const int c = e & 1023;
    float4 a = make_float4(0.f, 0.f, 0.f, 0.f);
    #pragma unroll
    for (int s = 0; s < KSPLIT; s++) {
        const float4 v = *reinterpret_cast<const float4*>(part + (size_t)s * NQ * HID + e);
        a.x += v.x; a.y += v.y; a.z += v.z; a.w += v.w;
    }
    const float inv = 1.0f / rs[r];
    float v4[4] = {a.x * inv, a.y * inv, a.z * inv, a.w * inv};
    float lo[4];
    #pragma unroll
    for (int j = 0; j < 4; j++) {
        __nv_bfloat16 h = __float2bfloat16(v4[j]);
        lo[j] = v4[j] - __bfloat162float(h);
    }
    const size_t o = (size_t)r * (2 * HID) + HID + c;
    uint2 uh, ul;
    uh.x = pack_bf2(v4[0], v4[1]); uh.y = pack_bf2(v4[2], v4[3]);
    ul.x = pack_bf2(lo[0], lo[1]); ul.y = pack_bf2(lo[2], lo[3]);
    *reinterpret_cast<uint2*>(ch + o) = uh;
    *reinterpret_cast<uint2*>(cl + o) = ul;
}

// ---------------- launch ----------------
#define DEVPTR(name, sym, type) \
    type* name; { void* p_ = nullptr; cudaGetSymbolAddress(&p_, sym); name = (type*)p_; }

#define SMEM_NS 147456   // 3 stages x 48KB (epilogue needs 134144)
#define SMEM_SP 196608   // 4 stages x 48KB

extern "C" void kernel_launch(void* const* d_in, const int* in_sizes, int n_in,
                              void* d_out, int out_size)
{
    (void)in_sizes; (void)n_in; (void)out_size;
    const float* query = (const float*)d_in[0];
    const float* W_in  = (const float*)d_in[1];
    const float* b_in  = (const float*)d_in[2];
    const float* W_e1  = (const float*)d_in[3];
    const float* b_e1  = (const float*)d_in[4];
    const float* W_e2  = (const float*)d_in[5];
    const float* b_e2  = (const float*)d_in[6];
    const float* W_k   = (const float*)d_in[7];
    const float* b_k   = (const float*)d_in[8];
    const float* mem_keys   = (const float*)d_in[9];
    const float* mem_values = (const float*)d_in[10];
    const float* W_r1  = (const float*)d_in[11];
    const float* b_r1  = (const float*)d_in[12];
    const float* W_r2  = (const float*)d_in[13];
    const float* b_r2  = (const float*)d_in[14];
    float* out = (float*)d_out;

    DEVPTR(qh, g_qh, __nv_bfloat16)     DEVPTR(ql, g_ql, __nv_bfloat16)
    DEVPTR(Winh, g_Winh, __nv_bfloat16) DEVPTR(Winl, g_Winl, __nv_bfloat16)
    DEVPTR(We1h, g_We1h, __nv_bfloat16) DEVPTR(We1l, g_We1l, __nv_bfloat16)
    DEVPTR(We2h, g_We2h, __nv_bfloat16) DEVPTR(We2l, g_We2l, __nv_bfloat16)
    DEVPTR(Wkh, g_Wkh, __nv_bfloat16)   DEVPTR(Wkl, g_Wkl, __nv_bfloat16)
    DEVPTR(Wr1h, g_Wr1h, __nv_bfloat16) DEVPTR(Wr1l, g_Wr1l, __nv_bfloat16)
    DEVPTR(Wr2h, g_Wr2h, __nv_bfloat16) DEVPTR(Wr2l, g_Wr2l, __nv_bfloat16)
    DEVPTR(MK, g_MK, __nv_bfloat16)     DEVPTR(MVT, g_MVT, __nv_bfloat16)
    DEVPTR(xh, g_xh, __nv_bfloat16)     DEVPTR(xl, g_xl, __nv_bfloat16)
    DEVPTR(hh, g_hh, __nv_bfloat16)     DEVPTR(hl, g_hl, __nv_bfloat16)
    DEVPTR(ch, g_ch, __nv_bfloat16)     DEVPTR(cl, g_cl, __nv_bfloat16)
    DEVPTR(key, g_key, __nv_bfloat16)
    DEVPTR(P, g_P, __nv_bfloat16)
    DEVPTR(rh, g_rh, __nv_bfloat16)     DEVPTR(rl, g_rl, __nv_bfloat16)
    DEVPTR(part, g_part, float)
    DEVPTR(prs, g_prs, float)
    DEVPTR(rowsum, g_rowsum, float)

    cudaFuncSetAttribute(gemm_hmma<0,true,false>,  cudaFuncAttributeMaxDynamicSharedMemorySize, SMEM_SP);
    cudaFuncSetAttribute(gemm_hmma<1,true,false>,  cudaFuncAttributeMaxDynamicSharedMemorySize, SMEM_SP);
    cudaFuncSetAttribute(gemm_hmma<2,true,false>,  cudaFuncAttributeMaxDynamicSharedMemorySize, SMEM_SP);
    cudaFuncSetAttribute(gemm_hmma<3,true,false>,  cudaFuncAttributeMaxDynamicSharedMemorySize, SMEM_SP);
    cudaFuncSetAttribute(gemm_hmma<4,false,false>, cudaFuncAttributeMaxDynamicSharedMemorySize, SMEM_NS);
    cudaFuncSetAttribute(gemm_hmma<0,false,true>,  cudaFuncAttributeMaxDynamicSharedMemorySize, SMEM_NS);

    // ---- conversions ----
    k_split<<<(NQ*EMB + 255) / 256, 256>>>(query, qh, ql, NQ*EMB);
    k_split_t<<<dim3(HID/32,  EMB/32),   dim3(32,8)>>>(W_in, Winh, Winl, EMB,   HID);
    k_split_t<<<dim3(2*HID/32, HID/32),  dim3(32,8)>>>(W_e1, We1h, We1l, HID,   2*HID);
    k_split_t<<<dim3(HID/32,  2*HID/32), dim3(32,8)>>>(W_e2, We2h, We2l, 2*HID, HID);
    k_split_t<<<dim3(HID/32,  HID/32),   dim3(32,8)>>>(W_k,  Wkh,  Wkl,  HID,   HID);
    k_split_t<<<dim3(2*HID/32, 2*HID/32),dim3(32,8)>>>(W_r1, Wr1h, Wr1l, 2*HID, 2*HID);
    k_split_t<<<dim3(EMB/32,  2*HID/32), dim3(32,8)>>>(W_r2, Wr2h, Wr2l, 2*HID, EMB);
    k_tobf16<<<8192, 256>>>(mem_keys, MK, (size_t)MEM * HID);
    k_transpose_bf16<<<dim3(HID/32, MEM/32), dim3(32, 8)>>>(mem_values, MVT);

    // ---- GEMM chain (all B operands are [N][K]) ----
    // x = query @ W_in + b_in
    gemm_hmma<1,true,false><<<dim3(NQ/BM, HID/BN), 512, SMEM_SP>>>(
        qh, ql, Winh, Winl, b_in, nullptr, xh, xl, nullptr, 0.f, EMB, EMB, EMB, HID, 0);
    // h = gelu(x @ W_e1 + b_e1)
    gemm_hmma<2,true,false><<<dim3(NQ/BM, 2*HID/BN), 512, SMEM_SP>>>(
        xh, xl, We1h, We1l, b_e1, nullptr, hh, hl, nullptr, 0.f, HID, HID, HID, 2*HID, 0);
    // encoded = h @ W_e2 + b_e2 -> combined[:, 0:HID]
    gemm_hmma<1,true,false><<<dim3(NQ/BM, HID/BN), 512, SMEM_SP>>>(
        hh, hl, We2h, We2l, b_e2, nullptr, ch, cl, nullptr, 0.f,
        2*HID, 2*HID, 2*HID, 2*HID, 0);
    // key = encoded @ W_k + b_k  (A = combined left half)
    gemm_hmma<3,true,false><<<dim3(NQ/BM, HID/BN), 512, SMEM_SP>>>(
        ch, cl, Wkh, Wkl, b_k, nullptr, key, nullptr, nullptr, 0.f,
        HID, 2*HID, HID, HID, 0);
    // P = exp((key @ mem_keys^T) / 32), fused per-tile rowsum partials
    // grid m-fastest: concurrent CTAs share the streaming B tile, A stays in L2
    gemm_hmma<4,false,false><<<dim3(NQ/BM, MEM/BN), 512, SMEM_NS>>>(
        key, nullptr, MK, nullptr, nullptr, nullptr, P, nullptr, prs, 0.03125f,
        HID, HID, HID, MEM, 0);
    // rowsum (deterministic reduce of partials)
    k_rsreduce<<<NQ/8, 256>>>(prs, rowsum);
    // retrieved partials: split-K over MEM; grid n-fastest so CTAs sharing a P tile run together
    gemm_hmma<0,false,true><<<dim3(HID/BN, NQ/BM, KSPLIT), 512, SMEM_NS>>>(
        P, nullptr, MVT, nullptr, nullptr, part, nullptr, nullptr, nullptr, 0.f,
        MEM/KSPLIT, MEM, MEM, HID, (size_t)NQ * HID);
    // combine + 1/rowsum -> combined[:, HID:2*HID]
    k_combine<<<NQ*HID/4/256, 256>>>(part, rowsum, ch, cl);
    // r = gelu(combined @ W_r1 + b_r1)
    gemm_hmma<2,true,false><<<dim3(NQ/BM, 2*HID/BN), 512, SMEM_SP>>>(
        ch, cl, Wr1h, Wr1l, b_r1, nullptr, rh, rl, nullptr, 0.f,
        2*HID, 2*HID, 2*HID, 2*HID, 0);
    // result = r @ W_r2 + b_r2 -> fp32 out
    gemm_hmma<0,true,false><<<dim3(NQ/BM, EMB/BN), 512, SMEM_SP>>>(
        rh, rl, Wr2h, Wr2l, b_r2, out, nullptr, nullptr, nullptr, 0.f,
        2*HID, 2*HID, 2*HID, EMB, 0);
}